// round 10
// baseline (speedup 1.0000x reference)
#include <cuda_runtime.h>
#include <cstdint>

// Problem constants (B=4, H=16, S=2048, D=64, fp32)
#define NBH   64
#define SEQ   2048
#define HD    64
#define BM    128         // query rows per CTA (4 warps x two 16-row m-tiles)
#define BN    64          // keys per tile
#define QST   68          // Q smem row stride (words)
#define KST   68          // K smem row stride
#define VST   72          // V smem row stride
#define NT    (SEQ / BN)  // 32 tiles

#define ELEMS (NBH * SEQ * HD)            // 8,388,608 per tensor

// Pre-converted tf32 operands (Q pre-scaled by 1/sqrt(D)) — 33.5 MB each.
__device__ unsigned g_Qc[ELEMS];
__device__ unsigned g_Kc[ELEMS];
__device__ unsigned g_Vc[ELEMS];

// smem: Q | K0 | K1 | V0 | V1
#define SM_Q  0
#define SM_K0 (BM * QST)
#define SM_K1 (SM_K0 + BN * KST)
#define SM_V0 (SM_K1 + BN * KST)
#define SM_V1 (SM_V0 + BN * VST)
#define SMEM_WORDS (SM_V1 + BN * VST)     // 26624
#define SMEM_BYTES (SMEM_WORDS * 4)       // 106496

__device__ __forceinline__ unsigned f2tf(float f) {
    unsigned r;
    asm("cvt.rna.tf32.f32 %0, %1;" : "=r"(r) : "f"(f));
    return r;
}

__device__ __forceinline__ void mma_tf32(float c[4],
                                         unsigned a0, unsigned a1, unsigned a2, unsigned a3,
                                         unsigned b0, unsigned b1) {
    asm volatile(
        "mma.sync.aligned.m16n8k8.row.col.f32.tf32.tf32.f32 "
        "{%0,%1,%2,%3}, {%4,%5,%6,%7}, {%8,%9}, {%0,%1,%2,%3};"
        : "+f"(c[0]), "+f"(c[1]), "+f"(c[2]), "+f"(c[3])
        : "r"(a0), "r"(a1), "r"(a2), "r"(a3), "r"(b0), "r"(b1));
}

__device__ __forceinline__ void ldsm_x4(unsigned& r0, unsigned& r1, unsigned& r2, unsigned& r3,
                                        unsigned saddr) {
    asm volatile("ldmatrix.sync.aligned.m8n8.x4.shared.b16 {%0,%1,%2,%3}, [%4];"
                 : "=r"(r0), "=r"(r1), "=r"(r2), "=r"(r3) : "r"(saddr));
}

#define CP16(dst_u32, src_ptr) \
    asm volatile("cp.async.cg.shared.global [%0], [%1], 16;" :: "r"(dst_u32), "l"(src_ptr))
#define CP_COMMIT() asm volatile("cp.async.commit_group;")
#define CP_WAIT0()  asm volatile("cp.async.wait_group 0;" ::: "memory")

// ---------------- prepass: fp32 -> tf32 bits (Q scaled) ----------------
__global__ void prepass(const float4* __restrict__ Q,
                        const float4* __restrict__ K,
                        const float4* __restrict__ V) {
    const int n4 = ELEMS / 4;
    uint4* q = (uint4*)g_Qc;
    uint4* k = (uint4*)g_Kc;
    uint4* v = (uint4*)g_Vc;
    for (int i = blockIdx.x * blockDim.x + threadIdx.x; i < n4;
         i += gridDim.x * blockDim.x) {
        float4 a = Q[i];
        q[i] = make_uint4(f2tf(0.125f * a.x), f2tf(0.125f * a.y),
                          f2tf(0.125f * a.z), f2tf(0.125f * a.w));
        float4 b = K[i];
        k[i] = make_uint4(f2tf(b.x), f2tf(b.y), f2tf(b.z), f2tf(b.w));
        float4 c = V[i];
        v[i] = make_uint4(f2tf(c.x), f2tf(c.y), f2tf(c.z), f2tf(c.w));
    }
}

// ---------------- main flash kernel ----------------
__global__ __launch_bounds__(128)
void flash_sdpa_tf32_v3(float* __restrict__ O) {
    extern __shared__ unsigned smu[];
    const int tid  = threadIdx.x;
    const int warp = tid >> 5;
    const int lane = tid & 31;
    const int gr   = lane >> 2;
    const int gc   = lane & 3;
    const int bh    = blockIdx.y;
    const int mbase = blockIdx.x * BM;

    unsigned sbase = (unsigned)__cvta_generic_to_shared(smu);
    const unsigned Qs_b = sbase + SM_Q  * 4u;
    const unsigned K_b[2] = { sbase + SM_K0 * 4u, sbase + SM_K1 * 4u };
    const unsigned V_b[2] = { sbase + SM_V0 * 4u, sbase + SM_V1 * 4u };

    // ---- per-lane LDSM addressing precompute ----
    const int l8 = lane & 7;
    const int qrow_l = warp * 32 + l8 + ((lane & 8) ? 8 : 0);
    const int qcol_l = ((lane >> 4) & 1) * 4;
    const int kap    = (l8 >> 1) + ((l8 & 1) << 2);     // key permutation
    const int kg     = lane >> 3;
    const int krow_l = ((kg >> 1) << 3) + kap;
    const int kcol_l = (kg & 1) * 4;

    const uint4* qg = (const uint4*)g_Qc + ((size_t)bh * SEQ + mbase) * (HD / 4);
    const uint4* kg4 = (const uint4*)g_Kc + (size_t)bh * SEQ * (HD / 4);
    const uint4* vg4 = (const uint4*)g_Vc + (size_t)bh * SEQ * (HD / 4);

    // ---- issue Q staging (once) + tile 0 K/V, one commit group ----
#pragma unroll
    for (int i = 0; i < 16; i++) {
        int idx = tid + i * 128;                  // 0..2047 uint4
        int r = idx >> 4, c4 = idx & 15;
        CP16(Qs_b + (unsigned)((r * QST + c4 * 4) * 4), qg + idx);
    }
#pragma unroll
    for (int i = 0; i < 8; i++) {
        int idx = tid + i * 128;                  // 0..1023 uint4
        int r = idx >> 4, c4 = idx & 15;
        CP16(K_b[0] + (unsigned)((r * KST + c4 * 4) * 4), kg4 + idx);
        CP16(V_b[0] + (unsigned)((r * VST + c4 * 4) * 4), vg4 + idx);
    }
    CP_COMMIT();

    float o[2][8][4];
#pragma unroll
    for (int mt = 0; mt < 2; mt++)
#pragma unroll
        for (int nt = 0; nt < 8; nt++) { o[mt][nt][0]=0.f; o[mt][nt][1]=0.f; o[mt][nt][2]=0.f; o[mt][nt][3]=0.f; }
    float mrow[2][2] = {{-1e30f,-1e30f},{-1e30f,-1e30f}};
    float lrow[2][2] = {{0.f,0.f},{0.f,0.f}};

    for (int t = 0; t < NT; t++) {
        const int cur = t & 1, nxt = cur ^ 1;
        CP_WAIT0();
        __syncthreads();   // tile t resident; all reads of buffer 'nxt' (tile t-1) done

        if (t + 1 < NT) {
#pragma unroll
            for (int i = 0; i < 8; i++) {
                int idx = tid + i * 128;
                int r = idx >> 4, c4 = idx & 15;
                CP16(K_b[nxt] + (unsigned)((r * KST + c4 * 4) * 4),
                     kg4 + (t + 1) * (BN * HD / 4) + idx);
                CP16(V_b[nxt] + (unsigned)((r * VST + c4 * 4) * 4),
                     vg4 + (t + 1) * (BN * HD / 4) + idx);
            }
            CP_COMMIT();
        }

        const unsigned Ks_b = K_b[cur];
        const unsigned* Vsb = smu + (cur ? SM_V1 : SM_V0);

        // ---- S = (Q*scale) @ K^T with permuted key columns ----
        float s[2][8][4];
#pragma unroll
        for (int mt = 0; mt < 2; mt++)
#pragma unroll
            for (int nt = 0; nt < 8; nt++) { s[mt][nt][0]=0.f; s[mt][nt][1]=0.f; s[mt][nt][2]=0.f; s[mt][nt][3]=0.f; }

#pragma unroll
        for (int kt = 0; kt < 8; kt++) {
            unsigned kb[16];
#pragma unroll
            for (int ntp = 0; ntp < 4; ntp++) {
                unsigned addr = Ks_b + (unsigned)(((ntp * 16 + krow_l) * KST + kcol_l + kt * 8) * 4);
                ldsm_x4(kb[ntp*4+0], kb[ntp*4+1], kb[ntp*4+2], kb[ntp*4+3], addr);
            }
#pragma unroll
            for (int mt = 0; mt < 2; mt++) {
                unsigned a0, a1, a2, a3;
                unsigned qaddr = Qs_b + (unsigned)(((qrow_l + mt * 16) * QST + qcol_l + kt * 8) * 4);
                ldsm_x4(a0, a1, a2, a3, qaddr);
#pragma unroll
                for (int nt = 0; nt < 8; nt++) {
                    unsigned b0 = kb[(nt >> 1) * 4 + (nt & 1) * 2];
                    unsigned b1 = kb[(nt >> 1) * 4 + (nt & 1) * 2 + 1];
                    mma_tf32(s[mt][nt], a0, a1, a2, a3, b0, b1);
                }
            }
        }

        // ---- online softmax; P -> tf32 bits in registers ----
#pragma unroll
        for (int mt = 0; mt < 2; mt++) {
            float mx0 = -1e30f, mx1 = -1e30f;
#pragma unroll
            for (int nt = 0; nt < 8; nt++) {
                mx0 = fmaxf(mx0, fmaxf(s[mt][nt][0], s[mt][nt][1]));
                mx1 = fmaxf(mx1, fmaxf(s[mt][nt][2], s[mt][nt][3]));
            }
            mx0 = fmaxf(mx0, __shfl_xor_sync(0xffffffffu, mx0, 1));
            mx0 = fmaxf(mx0, __shfl_xor_sync(0xffffffffu, mx0, 2));
            mx1 = fmaxf(mx1, __shfl_xor_sync(0xffffffffu, mx1, 1));
            mx1 = fmaxf(mx1, __shfl_xor_sync(0xffffffffu, mx1, 2));

            float mn0 = fmaxf(mrow[mt][0], mx0), mn1 = fmaxf(mrow[mt][1], mx1);
            float cr0 = __expf(mrow[mt][0] - mn0), cr1 = __expf(mrow[mt][1] - mn1);
            mrow[mt][0] = mn0; mrow[mt][1] = mn1;

            float ps0 = 0.f, ps1 = 0.f;
#pragma unroll
            for (int nt = 0; nt < 8; nt++) {
                float e0 = __expf(s[mt][nt][0] - mn0);
                float e1 = __expf(s[mt][nt][1] - mn0);
                float e2 = __expf(s[mt][nt][2] - mn1);
                float e3 = __expf(s[mt][nt][3] - mn1);
                ps0 += e0 + e1; ps1 += e2 + e3;
                s[mt][nt][0] = __uint_as_float(f2tf(e0));
                s[mt][nt][1] = __uint_as_float(f2tf(e1));
                s[mt][nt][2] = __uint_as_float(f2tf(e2));
                s[mt][nt][3] = __uint_as_float(f2tf(e3));
                o[mt][nt][0] *= cr0; o[mt][nt][1] *= cr0;
                o[mt][nt][2] *= cr1; o[mt][nt][3] *= cr1;
            }
            lrow[mt][0] = lrow[mt][0] * cr0 + ps0;
            lrow[mt][1] = lrow[mt][1] * cr1 + ps1;
        }

        // ---- O += P @ V (P A-frags alias S output via kappa) ----
#pragma unroll
        for (int kt = 0; kt < 8; kt++) {
            unsigned vb[16];
#pragma unroll
            for (int nt = 0; nt < 8; nt++) {
                vb[nt*2]   = Vsb[(kt * 8 + gc    ) * VST + nt * 8 + gr];
                vb[nt*2+1] = Vsb[(kt * 8 + gc + 4) * VST + nt * 8 + gr];
            }
#pragma unroll
            for (int mt = 0; mt < 2; mt++) {
                unsigned a0 = __float_as_uint(s[mt][kt][0]);
                unsigned a1 = __float_as_uint(s[mt][kt][2]);
                unsigned a2 = __float_as_uint(s[mt][kt][1]);
                unsigned a3 = __float_as_uint(s[mt][kt][3]);
#pragma unroll
                for (int nt = 0; nt < 8; nt++)
                    mma_tf32(o[mt][nt], a0, a1, a2, a3, vb[nt*2], vb[nt*2+1]);
            }
        }
    }

    // ---- epilogue ----
#pragma unroll
    for (int mt = 0; mt < 2; mt++) {
        float l0 = lrow[mt][0], l1 = lrow[mt][1];
        l0 += __shfl_xor_sync(0xffffffffu, l0, 1);
        l0 += __shfl_xor_sync(0xffffffffu, l0, 2);
        l1 += __shfl_xor_sync(0xffffffffu, l1, 1);
        l1 += __shfl_xor_sync(0xffffffffu, l1, 2);
        float inv0 = 1.f / l0, inv1 = 1.f / l1;

        float* op = O + ((size_t)bh * SEQ + mbase + warp * 32 + mt * 16) * HD;
#pragma unroll
        for (int nt = 0; nt < 8; nt++) {
            *(float2*)&op[ gr      * HD + nt * 8 + 2 * gc] =
                make_float2(o[mt][nt][0] * inv0, o[mt][nt][1] * inv0);
            *(float2*)&op[(gr + 8) * HD + nt * 8 + 2 * gc] =
                make_float2(o[mt][nt][2] * inv1, o[mt][nt][3] * inv1);
        }
    }
}

extern "C" void kernel_launch(void* const* d_in, const int* in_sizes, int n_in,
                              void* d_out, int out_size) {
    (void)in_sizes; (void)n_in; (void)out_size;
    const float4* Q = (const float4*)d_in[0];
    const float4* K = (const float4*)d_in[1];
    const float4* V = (const float4*)d_in[2];
    float* O = (float*)d_out;

    prepass<<<1184, 256>>>(Q, K, V);

    static int attr_set = 0;
    if (!attr_set) {
        cudaFuncSetAttribute(flash_sdpa_tf32_v3,
                             cudaFuncAttributeMaxDynamicSharedMemorySize, SMEM_BYTES);
        attr_set = 1;
    }
    dim3 grid(SEQ / BM, NBH);   // 16 x 64 = 1024 CTAs
    flash_sdpa_tf32_v3<<<grid, 128, SMEM_BYTES>>>(O);
}

// round 11
// speedup vs baseline: 1.0251x; 1.0251x over previous
#include <cuda_runtime.h>
#include <cstdint>

// Problem constants (B=4, H=16, S=2048, D=64, fp32)
#define NBH   64
#define SEQ   2048
#define HD    64
#define BM    128         // query rows per CTA (4 warps x two 16-row m-tiles)
#define BN    32          // keys per tile (halved -> 3 CTAs/SM)
#define QST   68          // Q smem row stride (words)
#define KST   68          // K smem row stride
#define VST   72          // V smem row stride
#define NT    (SEQ / BN)  // 64 tiles

#define ELEMS (NBH * SEQ * HD)            // 8,388,608 per tensor

// Pre-converted tf32 operands for K/V — 33.5 MB each.
__device__ unsigned g_Kc[ELEMS];
__device__ unsigned g_Vc[ELEMS];

// smem: Q | K0 | K1 | V0 | V1
#define SM_Q  0
#define SM_K0 (BM * QST)                  // 8704
#define SM_K1 (SM_K0 + BN * KST)          // +2176
#define SM_V0 (SM_K1 + BN * KST)
#define SM_V1 (SM_V0 + BN * VST)          // +2304
#define SMEM_WORDS (SM_V1 + BN * VST)     // 17664
#define SMEM_BYTES (SMEM_WORDS * 4)       // 70656  -> 3 CTAs/SM (211968 <= 228KB)

__device__ __forceinline__ unsigned f2tf(float f) {
    unsigned r;
    asm("cvt.rna.tf32.f32 %0, %1;" : "=r"(r) : "f"(f));
    return r;
}

__device__ __forceinline__ void mma_tf32(float c[4],
                                         unsigned a0, unsigned a1, unsigned a2, unsigned a3,
                                         unsigned b0, unsigned b1) {
    asm volatile(
        "mma.sync.aligned.m16n8k8.row.col.f32.tf32.tf32.f32 "
        "{%0,%1,%2,%3}, {%4,%5,%6,%7}, {%8,%9}, {%0,%1,%2,%3};"
        : "+f"(c[0]), "+f"(c[1]), "+f"(c[2]), "+f"(c[3])
        : "r"(a0), "r"(a1), "r"(a2), "r"(a3), "r"(b0), "r"(b1));
}

__device__ __forceinline__ void ldsm_x4(unsigned& r0, unsigned& r1, unsigned& r2, unsigned& r3,
                                        unsigned saddr) {
    asm volatile("ldmatrix.sync.aligned.m8n8.x4.shared.b16 {%0,%1,%2,%3}, [%4];"
                 : "=r"(r0), "=r"(r1), "=r"(r2), "=r"(r3) : "r"(saddr));
}

#define CP16(dst_u32, src_ptr) \
    asm volatile("cp.async.cg.shared.global [%0], [%1], 16;" :: "r"(dst_u32), "l"(src_ptr))
#define CP_COMMIT() asm volatile("cp.async.commit_group;")
#define CP_WAIT0()  asm volatile("cp.async.wait_group 0;" ::: "memory")

// ---------------- prepass: K/V fp32 -> tf32 bits ----------------
__global__ void prepass_kv(const float4* __restrict__ K,
                           const float4* __restrict__ V) {
    const int n4 = ELEMS / 4;
    uint4* k = (uint4*)g_Kc;
    uint4* v = (uint4*)g_Vc;
    for (int i = blockIdx.x * blockDim.x + threadIdx.x; i < n4;
         i += gridDim.x * blockDim.x) {
        float4 b = K[i];
        k[i] = make_uint4(f2tf(b.x), f2tf(b.y), f2tf(b.z), f2tf(b.w));
        float4 c = V[i];
        v[i] = make_uint4(f2tf(c.x), f2tf(c.y), f2tf(c.z), f2tf(c.w));
    }
}

// ---------------- main flash kernel ----------------
__global__ __launch_bounds__(128, 3)
void flash_sdpa_tf32_v4(const float* __restrict__ Q, float* __restrict__ O) {
    extern __shared__ unsigned smu[];
    const int tid  = threadIdx.x;
    const int warp = tid >> 5;
    const int lane = tid & 31;
    const int gr   = lane >> 2;
    const int gc   = lane & 3;
    const int bh    = blockIdx.y;
    const int mbase = blockIdx.x * BM;

    unsigned sbase = (unsigned)__cvta_generic_to_shared(smu);
    const unsigned Qs_b = sbase + SM_Q  * 4u;
    const unsigned K_b[2] = { sbase + SM_K0 * 4u, sbase + SM_K1 * 4u };

    // ---- per-lane LDSM addressing precompute ----
    const int l8 = lane & 7;
    const int qrow_l = warp * 32 + l8 + ((lane & 8) ? 8 : 0);
    const int qcol_l = ((lane >> 4) & 1) * 4;
    const int kap    = (l8 >> 1) + ((l8 & 1) << 2);     // key permutation
    const int kg     = lane >> 3;
    const int krow_l = ((kg >> 1) << 3) + kap;          // 0..15 within 16-row span
    const int kcol_l = (kg & 1) * 4;

    const uint4* kg4 = (const uint4*)g_Kc + (size_t)bh * SEQ * (HD / 4);
    const uint4* vg4 = (const uint4*)g_Vc + (size_t)bh * SEQ * (HD / 4);

    // ---- issue tile 0 K/V cp.async first (overlaps Q conversion below) ----
#pragma unroll
    for (int i = 0; i < 4; i++) {
        int idx = tid + i * 128;                  // 0..511 uint4
        int r = idx >> 4, c4 = idx & 15;
        CP16(K_b[0] + (unsigned)((r * KST + c4 * 4) * 4), kg4 + idx);
        CP16(sbase + (unsigned)((SM_V0 + r * VST + c4 * 4) * 4), vg4 + idx);
    }
    CP_COMMIT();

    // ---- stage Q once: tf32(0.125 * q) via LDG+cvt+STS ----
    {
        const float4* qp4 = (const float4*)(Q + ((size_t)bh * SEQ + mbase) * HD);
        unsigned* Qs = smu + SM_Q;
#pragma unroll
        for (int i = 0; i < 16; i++) {
            int idx = tid + i * 128;              // 0..2047 float4
            int r = idx >> 4, c4 = idx & 15;
            float4 q4 = qp4[idx];
            uint4 qu = { f2tf(0.125f * q4.x), f2tf(0.125f * q4.y),
                         f2tf(0.125f * q4.z), f2tf(0.125f * q4.w) };
            *(uint4*)&Qs[r * QST + c4 * 4] = qu;
        }
    }

    float o[2][8][4];
#pragma unroll
    for (int mt = 0; mt < 2; mt++)
#pragma unroll
        for (int nt = 0; nt < 8; nt++) { o[mt][nt][0]=0.f; o[mt][nt][1]=0.f; o[mt][nt][2]=0.f; o[mt][nt][3]=0.f; }
    float mrow[2][2] = {{-1e30f,-1e30f},{-1e30f,-1e30f}};
    float lrow[2][2] = {{0.f,0.f},{0.f,0.f}};

    for (int t = 0; t < NT; t++) {
        const int cur = t & 1, nxt = cur ^ 1;
        CP_WAIT0();
        __syncthreads();   // tile t resident; buffer 'nxt' reads (tile t-1) done; Q staged (t=0)

        if (t + 1 < NT) {
#pragma unroll
            for (int i = 0; i < 4; i++) {
                int idx = tid + i * 128;
                int r = idx >> 4, c4 = idx & 15;
                CP16(K_b[nxt] + (unsigned)((r * KST + c4 * 4) * 4),
                     kg4 + (t + 1) * (BN * HD / 4) + idx);
                CP16(sbase + (unsigned)(((nxt ? SM_V1 : SM_V0) + r * VST + c4 * 4) * 4),
                     vg4 + (t + 1) * (BN * HD / 4) + idx);
            }
            CP_COMMIT();
        }

        const unsigned Ks_b = K_b[cur];
        const unsigned* Vsb = smu + (cur ? SM_V1 : SM_V0);

        // ---- S = (Q*scale) @ K^T with permuted key columns (4 nt of 8 keys) ----
        float s[2][4][4];
#pragma unroll
        for (int mt = 0; mt < 2; mt++)
#pragma unroll
            for (int nt = 0; nt < 4; nt++) { s[mt][nt][0]=0.f; s[mt][nt][1]=0.f; s[mt][nt][2]=0.f; s[mt][nt][3]=0.f; }

#pragma unroll
        for (int kt = 0; kt < 8; kt++) {
            unsigned kb[8];
#pragma unroll
            for (int ntp = 0; ntp < 2; ntp++) {
                unsigned addr = Ks_b + (unsigned)(((ntp * 16 + krow_l) * KST + kcol_l + kt * 8) * 4);
                ldsm_x4(kb[ntp*4+0], kb[ntp*4+1], kb[ntp*4+2], kb[ntp*4+3], addr);
            }
#pragma unroll
            for (int mt = 0; mt < 2; mt++) {
                unsigned a0, a1, a2, a3;
                unsigned qaddr = Qs_b + (unsigned)(((qrow_l + mt * 16) * QST + qcol_l + kt * 8) * 4);
                ldsm_x4(a0, a1, a2, a3, qaddr);
#pragma unroll
                for (int nt = 0; nt < 4; nt++) {
                    unsigned b0 = kb[(nt >> 1) * 4 + (nt & 1) * 2];
                    unsigned b1 = kb[(nt >> 1) * 4 + (nt & 1) * 2 + 1];
                    mma_tf32(s[mt][nt], a0, a1, a2, a3, b0, b1);
                }
            }
        }

        // ---- online softmax; P -> tf32 bits in registers ----
#pragma unroll
        for (int mt = 0; mt < 2; mt++) {
            float mx0 = -1e30f, mx1 = -1e30f;
#pragma unroll
            for (int nt = 0; nt < 4; nt++) {
                mx0 = fmaxf(mx0, fmaxf(s[mt][nt][0], s[mt][nt][1]));
                mx1 = fmaxf(mx1, fmaxf(s[mt][nt][2], s[mt][nt][3]));
            }
            mx0 = fmaxf(mx0, __shfl_xor_sync(0xffffffffu, mx0, 1));
            mx0 = fmaxf(mx0, __shfl_xor_sync(0xffffffffu, mx0, 2));
            mx1 = fmaxf(mx1, __shfl_xor_sync(0xffffffffu, mx1, 1));
            mx1 = fmaxf(mx1, __shfl_xor_sync(0xffffffffu, mx1, 2));

            float mn0 = fmaxf(mrow[mt][0], mx0), mn1 = fmaxf(mrow[mt][1], mx1);
            float cr0 = __expf(mrow[mt][0] - mn0), cr1 = __expf(mrow[mt][1] - mn1);
            mrow[mt][0] = mn0; mrow[mt][1] = mn1;

            float ps0 = 0.f, ps1 = 0.f;
#pragma unroll
            for (int nt = 0; nt < 4; nt++) {
                float e0 = __expf(s[mt][nt][0] - mn0);
                float e1 = __expf(s[mt][nt][1] - mn0);
                float e2 = __expf(s[mt][nt][2] - mn1);
                float e3 = __expf(s[mt][nt][3] - mn1);
                ps0 += e0 + e1; ps1 += e2 + e3;
                s[mt][nt][0] = __uint_as_float(f2tf(e0));
                s[mt][nt][1] = __uint_as_float(f2tf(e1));
                s[mt][nt][2] = __uint_as_float(f2tf(e2));
                s[mt][nt][3] = __uint_as_float(f2tf(e3));
            }
#pragma unroll
            for (int nt = 0; nt < 8; nt++) {
                o[mt][nt][0] *= cr0; o[mt][nt][1] *= cr0;
                o[mt][nt][2] *= cr1; o[mt][nt][3] *= cr1;
            }
            lrow[mt][0] = lrow[mt][0] * cr0 + ps0;
            lrow[mt][1] = lrow[mt][1] * cr1 + ps1;
        }

        // ---- O += P @ V (P A-frags alias S output via kappa); kt over 4 key-groups ----
#pragma unroll
        for (int kt = 0; kt < 4; kt++) {
            unsigned vb[16];
#pragma unroll
            for (int nt = 0; nt < 8; nt++) {
                vb[nt*2]   = Vsb[(kt * 8 + gc    ) * VST + nt * 8 + gr];
                vb[nt*2+1] = Vsb[(kt * 8 + gc + 4) * VST + nt * 8 + gr];
            }
#pragma unroll
            for (int mt = 0; mt < 2; mt++) {
                unsigned a0 = __float_as_uint(s[mt][kt][0]);
                unsigned a1 = __float_as_uint(s[mt][kt][2]);
                unsigned a2 = __float_as_uint(s[mt][kt][1]);
                unsigned a3 = __float_as_uint(s[mt][kt][3]);
#pragma unroll
                for (int nt = 0; nt < 8; nt++)
                    mma_tf32(o[mt][nt], a0, a1, a2, a3, vb[nt*2], vb[nt*2+1]);
            }
        }
    }

    // ---- epilogue ----
#pragma unroll
    for (int mt = 0; mt < 2; mt++) {
        float l0 = lrow[mt][0], l1 = lrow[mt][1];
        l0 += __shfl_xor_sync(0xffffffffu, l0, 1);
        l0 += __shfl_xor_sync(0xffffffffu, l0, 2);
        l1 += __shfl_xor_sync(0xffffffffu, l1, 1);
        l1 += __shfl_xor_sync(0xffffffffu, l1, 2);
        float inv0 = 1.f / l0, inv1 = 1.f / l1;

        float* op = O + ((size_t)bh * SEQ + mbase + warp * 32 + mt * 16) * HD;
#pragma unroll
        for (int nt = 0; nt < 8; nt++) {
            *(float2*)&op[ gr      * HD + nt * 8 + 2 * gc] =
                make_float2(o[mt][nt][0] * inv0, o[mt][nt][1] * inv0);
            *(float2*)&op[(gr + 8) * HD + nt * 8 + 2 * gc] =
                make_float2(o[mt][nt][2] * inv1, o[mt][nt][3] * inv1);
        }
    }
}

extern "C" void kernel_launch(void* const* d_in, const int* in_sizes, int n_in,
                              void* d_out, int out_size) {
    (void)in_sizes; (void)n_in; (void)out_size;
    const float*  Q = (const float*)d_in[0];
    const float4* K = (const float4*)d_in[1];
    const float4* V = (const float4*)d_in[2];
    float* O = (float*)d_out;

    prepass_kv<<<1184, 256>>>(K, V);

    static int attr_set = 0;
    if (!attr_set) {
        cudaFuncSetAttribute(flash_sdpa_tf32_v4,
                             cudaFuncAttributeMaxDynamicSharedMemorySize, SMEM_BYTES);
        attr_set = 1;
    }
    dim3 grid(SEQ / BM, NBH);   // 16 x 64 = 1024 CTAs
    flash_sdpa_tf32_v4<<<grid, 128, SMEM_BYTES>>>(Q, O);
}

// round 14
// speedup vs baseline: 1.8624x; 1.8168x over previous
#include <cuda_runtime.h>
#include <cuda_fp16.h>
#include <cstdint>

// Problem constants (B=4, H=16, S=2048, D=64, fp32)
#define NBH   64
#define SEQ   2048
#define HD    64
#define BM    128         // query rows per CTA (4 warps x two 16-row m-tiles)
#define BN    64          // keys per tile
#define NT    (SEQ / BN)  // 32 tiles

#define QSTH  72          // smem row strides in halves (64 + 8 pad -> conflict-free ldsm)
#define KSTH  72
#define VSTH  72

#define ELEMS (NBH * SEQ * HD)            // 8,388,608 per tensor

// Pre-converted fp16 operands (Q pre-scaled by log2(e)/sqrt(D)) — 16.8 MB each.
__device__ __half g_Qh[ELEMS];
__device__ __half g_Kh[ELEMS];
__device__ __half g_Vh[ELEMS];

// smem layout in half units: Q | K0 | K1 | V0 | V1
#define SM_Q  0
#define SM_K0 (BM * QSTH)                 // 9216
#define SM_K1 (SM_K0 + BN * KSTH)         // +4608
#define SM_V0 (SM_K1 + BN * KSTH)
#define SM_V1 (SM_V0 + BN * VSTH)
#define SMEM_HALVES (SM_V1 + BN * VSTH)   // 27648
#define SMEM_BYTES  (SMEM_HALVES * 2)     // 55296 -> 3 CTAs/SM

#define QSCALE 0.18033688011112042f       // 0.125 * log2(e)

__device__ __forceinline__ unsigned pack_h2(float lo, float hi) {
    unsigned d;
    asm("cvt.rn.f16x2.f32 %0, %1, %2;" : "=r"(d) : "f"(hi), "f"(lo));
    return d;
}

__device__ __forceinline__ float fast_ex2(float x) {
    float y;
    asm("ex2.approx.ftz.f32 %0, %1;" : "=f"(y) : "f"(x));
    return y;
}

__device__ __forceinline__ void mma_f16(float c[4],
                                        unsigned a0, unsigned a1, unsigned a2, unsigned a3,
                                        unsigned b0, unsigned b1) {
    asm volatile(
        "mma.sync.aligned.m16n8k16.row.col.f32.f16.f16.f32 "
        "{%0,%1,%2,%3}, {%4,%5,%6,%7}, {%8,%9}, {%0,%1,%2,%3};"
        : "+f"(c[0]), "+f"(c[1]), "+f"(c[2]), "+f"(c[3])
        : "r"(a0), "r"(a1), "r"(a2), "r"(a3), "r"(b0), "r"(b1));
}

__device__ __forceinline__ void ldsm_x4(unsigned& r0, unsigned& r1, unsigned& r2, unsigned& r3,
                                        unsigned saddr) {
    asm volatile("ldmatrix.sync.aligned.m8n8.x4.shared.b16 {%0,%1,%2,%3}, [%4];"
                 : "=r"(r0), "=r"(r1), "=r"(r2), "=r"(r3) : "r"(saddr));
}

__device__ __forceinline__ void ldsm_x4_t(unsigned& r0, unsigned& r1, unsigned& r2, unsigned& r3,
                                          unsigned saddr) {
    asm volatile("ldmatrix.sync.aligned.m8n8.x4.trans.shared.b16 {%0,%1,%2,%3}, [%4];"
                 : "=r"(r0), "=r"(r1), "=r"(r2), "=r"(r3) : "r"(saddr));
}

#define CP16(dst_u32, src_ptr) \
    asm volatile("cp.async.cg.shared.global [%0], [%1], 16;" :: "r"(dst_u32), "l"(src_ptr))
#define CP_COMMIT() asm volatile("cp.async.commit_group;")
#define CP_WAIT0()  asm volatile("cp.async.wait_group 0;" ::: "memory")

// ---------------- prepass: fp32 -> fp16 (Q scaled by log2e/8) ----------------
__global__ void prepass_qkv(const float4* __restrict__ Q,
                            const float4* __restrict__ K,
                            const float4* __restrict__ V) {
    const int n8 = ELEMS / 8;             // one uint4 of halves per iteration
    uint4* q = (uint4*)g_Qh;
    uint4* k = (uint4*)g_Kh;
    uint4* v = (uint4*)g_Vh;
    for (int i = blockIdx.x * blockDim.x + threadIdx.x; i < n8;
         i += gridDim.x * blockDim.x) {
        float4 a0 = Q[2*i], a1 = Q[2*i+1];
        q[i] = make_uint4(pack_h2(QSCALE*a0.x, QSCALE*a0.y), pack_h2(QSCALE*a0.z, QSCALE*a0.w),
                          pack_h2(QSCALE*a1.x, QSCALE*a1.y), pack_h2(QSCALE*a1.z, QSCALE*a1.w));
        float4 b0 = K[2*i], b1 = K[2*i+1];
        k[i] = make_uint4(pack_h2(b0.x, b0.y), pack_h2(b0.z, b0.w),
                          pack_h2(b1.x, b1.y), pack_h2(b1.z, b1.w));
        float4 c0 = V[2*i], c1 = V[2*i+1];
        v[i] = make_uint4(pack_h2(c0.x, c0.y), pack_h2(c0.z, c0.w),
                          pack_h2(c1.x, c1.y), pack_h2(c1.z, c1.w));
    }
}

// ---------------- main flash kernel (fp16 mma, exp2-domain softmax) ----------------
__global__ __launch_bounds__(128, 3)
void flash_sdpa_f16(float* __restrict__ O) {
    extern __shared__ __half smh[];
    const int tid  = threadIdx.x;
    const int warp = tid >> 5;
    const int lane = tid & 31;
    const int gr   = lane >> 2;
    const int gc   = lane & 3;
    const int bh    = blockIdx.y;
    const int mbase = blockIdx.x * BM;

    unsigned sbase = (unsigned)__cvta_generic_to_shared(smh);
    const unsigned Qs_b = sbase + SM_Q  * 2u;
    const unsigned K_b[2] = { sbase + SM_K0 * 2u, sbase + SM_K1 * 2u };
    const unsigned V_b[2] = { sbase + SM_V0 * 2u, sbase + SM_V1 * 2u };

    // ---- per-lane ldmatrix addressing ----
    const int l8 = lane & 7;
    // Q (A, non-trans): m0=(r0-7,klo) m1=(r8-15,klo) m2=(r0-7,khi) m3=(r8-15,khi)
    const int qrow_l = warp * 32 + ((lane & 8) ? 8 : 0) + l8;
    const int qcol_l = ((lane >> 4) & 1) * 8;
    // K (B, non-trans): m0=(n0-7,klo) m1=(n0-7,khi) m2=(n8-15,klo) m3=(n8-15,khi)
    const int krow_l = ((lane >> 4) & 1) * 8 + l8;
    const int kcol_l = ((lane >> 3) & 1) * 8;
    // V (B, trans): m0=(k0-7,dlo) m1=(k8-15,dlo) m2=(k0-7,dhi) m3=(k8-15,dhi)
    const int vrow_l = ((lane & 8) ? 8 : 0) + l8;
    const int vcol_l = ((lane >> 4) & 1) * 8;

    const uint4* qg = (const uint4*)g_Qh + ((size_t)bh * SEQ + mbase) * (HD / 8);
    const uint4* kg = (const uint4*)g_Kh + (size_t)bh * SEQ * (HD / 8);
    const uint4* vg = (const uint4*)g_Vh + (size_t)bh * SEQ * (HD / 8);

    // ---- stage Q (once) + tile 0 K/V via cp.async, one commit group ----
#pragma unroll
    for (int i = 0; i < 8; i++) {
        int idx = tid + i * 128;                  // 0..1023 uint4 (128 rows x 8)
        int r = idx >> 3, c = idx & 7;
        CP16(Qs_b + (unsigned)((r * QSTH + c * 8) * 2), qg + idx);
    }
#pragma unroll
    for (int i = 0; i < 4; i++) {
        int idx = tid + i * 128;                  // 0..511 uint4 (64 rows x 8)
        int r = idx >> 3, c = idx & 7;
        CP16(K_b[0] + (unsigned)((r * KSTH + c * 8) * 2), kg + idx);
        CP16(V_b[0] + (unsigned)((r * VSTH + c * 8) * 2), vg + idx);
    }
    CP_COMMIT();

    float o[2][8][4];
#pragma unroll
    for (int mt = 0; mt < 2; mt++)
#pragma unroll
        for (int nt = 0; nt < 8; nt++) { o[mt][nt][0]=0.f; o[mt][nt][1]=0.f; o[mt][nt][2]=0.f; o[mt][nt][3]=0.f; }
    float mrow[2][2] = {{-1e30f,-1e30f},{-1e30f,-1e30f}};
    float lrow[2][2] = {{0.f,0.f},{0.f,0.f}};

    for (int t = 0; t < NT; t++) {
        const int cur = t & 1, nxt = cur ^ 1;
        CP_WAIT0();
        __syncthreads();   // tile t resident; buffer 'nxt' (tile t-1) reads done

        if (t + 1 < NT) {
#pragma unroll
            for (int i = 0; i < 4; i++) {
                int idx = tid + i * 128;
                int r = idx >> 3, c = idx & 7;
                CP16(K_b[nxt] + (unsigned)((r * KSTH + c * 8) * 2),
                     kg + (t + 1) * (BN * HD / 8) + idx);
                CP16(V_b[nxt] + (unsigned)((r * VSTH + c * 8) * 2),
                     vg + (t + 1) * (BN * HD / 8) + idx);
            }
            CP_COMMIT();
        }

        const unsigned Ks_b = K_b[cur];
        const unsigned Vs_b = V_b[cur];

        // ---- S = Q' @ K^T  (scores in log2 domain; fp32 accum) ----
        float s[2][8][4];
#pragma unroll
        for (int mt = 0; mt < 2; mt++)
#pragma unroll
            for (int nt = 0; nt < 8; nt++) { s[mt][nt][0]=0.f; s[mt][nt][1]=0.f; s[mt][nt][2]=0.f; s[mt][nt][3]=0.f; }

#pragma unroll
        for (int kt = 0; kt < 4; kt++) {          // k16 steps over D=64
            unsigned kb[16];
#pragma unroll
            for (int ntp = 0; ntp < 4; ntp++) {   // 16 keys per ldsm.x4
                unsigned addr = Ks_b + (unsigned)(((ntp * 16 + krow_l) * KSTH + kt * 16 + kcol_l) * 2);
                ldsm_x4(kb[ntp*4+0], kb[ntp*4+1], kb[ntp*4+2], kb[ntp*4+3], addr);
            }
#pragma unroll
            for (int mt = 0; mt < 2; mt++) {
                unsigned a0, a1, a2, a3;
                unsigned qaddr = Qs_b + (unsigned)(((qrow_l + mt * 16) * QSTH + kt * 16 + qcol_l) * 2);
                ldsm_x4(a0, a1, a2, a3, qaddr);
#pragma unroll
                for (int nt = 0; nt < 8; nt++) {
                    // kb[ntp*4 + {b0 even-group, b1 even, b0 odd, b1 odd}]
                    unsigned b0 = kb[(nt >> 1) * 4 + (nt & 1) * 2];
                    unsigned b1 = kb[(nt >> 1) * 4 + (nt & 1) * 2 + 1];
                    mma_f16(s[mt][nt], a0, a1, a2, a3, b0, b1);
                }
            }
        }

        // ---- online softmax (base-2); P packed to half2 regs ----
        unsigned ph[2][8][2];
#pragma unroll
        for (int mt = 0; mt < 2; mt++) {
            float mx0 = -1e30f, mx1 = -1e30f;
#pragma unroll
            for (int nt = 0; nt < 8; nt++) {
                mx0 = fmaxf(mx0, fmaxf(s[mt][nt][0], s[mt][nt][1]));
                mx1 = fmaxf(mx1, fmaxf(s[mt][nt][2], s[mt][nt][3]));
            }
            mx0 = fmaxf(mx0, __shfl_xor_sync(0xffffffffu, mx0, 1));
            mx0 = fmaxf(mx0, __shfl_xor_sync(0xffffffffu, mx0, 2));
            mx1 = fmaxf(mx1, __shfl_xor_sync(0xffffffffu, mx1, 1));
            mx1 = fmaxf(mx1, __shfl_xor_sync(0xffffffffu, mx1, 2));

            float mn0 = fmaxf(mrow[mt][0], mx0), mn1 = fmaxf(mrow[mt][1], mx1);
            float cr0 = fast_ex2(mrow[mt][0] - mn0), cr1 = fast_ex2(mrow[mt][1] - mn1);
            mrow[mt][0] = mn0; mrow[mt][1] = mn1;

            float ps0 = 0.f, ps1 = 0.f;
#pragma unroll
            for (int nt = 0; nt < 8; nt++) {
                float e0 = fast_ex2(s[mt][nt][0] - mn0);
                float e1 = fast_ex2(s[mt][nt][1] - mn0);
                float e2 = fast_ex2(s[mt][nt][2] - mn1);
                float e3 = fast_ex2(s[mt][nt][3] - mn1);
                ps0 += e0 + e1; ps1 += e2 + e3;
                ph[mt][nt][0] = pack_h2(e0, e1);   // row gr   : keys 2gc,2gc+1
                ph[mt][nt][1] = pack_h2(e2, e3);   // row gr+8
            }
#pragma unroll
            for (int nt = 0; nt < 8; nt++) {
                o[mt][nt][0] *= cr0; o[mt][nt][1] *= cr0;
                o[mt][nt][2] *= cr1; o[mt][nt][3] *= cr1;
            }
            lrow[mt][0] = lrow[mt][0] * cr0 + ps0;
            lrow[mt][1] = lrow[mt][1] * cr1 + ps1;
        }

        // ---- O += P @ V  (A frags alias ph directly; k16 over keys) ----
#pragma unroll
        for (int ktp = 0; ktp < 4; ktp++) {       // 16 keys per step
            unsigned vb[16];
#pragma unroll
            for (int dp = 0; dp < 4; dp++) {      // 16 d-cols per ldsm.x4.trans
                unsigned addr = Vs_b + (unsigned)(((ktp * 16 + vrow_l) * VSTH + dp * 16 + vcol_l) * 2);
                ldsm_x4_t(vb[dp*4+0], vb[dp*4+1], vb[dp*4+2], vb[dp*4+3], addr);
            }
#pragma unroll
            for (int mt = 0; mt < 2; mt++) {
                unsigned a0 = ph[mt][2*ktp    ][0];
                unsigned a1 = ph[mt][2*ktp    ][1];
                unsigned a2 = ph[mt][2*ktp + 1][0];
                unsigned a3 = ph[mt][2*ktp + 1][1];
#pragma unroll
                for (int nt = 0; nt < 8; nt++) {
                    unsigned b0 = vb[(nt >> 1) * 4 + (nt & 1) * 2];
                    unsigned b1 = vb[(nt >> 1) * 4 + (nt & 1) * 2 + 1];
                    mma_f16(o[mt][nt], a0, a1, a2, a3, b0, b1);
                }
            }
        }
    }

    // ---- epilogue ----
#pragma unroll
    for (int mt = 0; mt < 2; mt++) {
        float l0 = lrow[mt][0], l1 = lrow[mt][1];
        l0 += __shfl_xor_sync(0xffffffffu, l0, 1);
        l0 += __shfl_xor_sync(0xffffffffu, l0, 2);
        l1 += __shfl_xor_sync(0xffffffffu, l1, 1);
        l1 += __shfl_xor_sync(0xffffffffu, l1, 2);
        float inv0 = 1.f / l0, inv1 = 1.f / l1;

        float* op = O + ((size_t)bh * SEQ + mbase + warp * 32 + mt * 16) * HD;
#pragma unroll
        for (int nt = 0; nt < 8; nt++) {
            *(float2*)&op[ gr      * HD + nt * 8 + 2 * gc] =
                make_float2(o[mt][nt][0] * inv0, o[mt][nt][1] * inv0);
            *(float2*)&op[(gr + 8) * HD + nt * 8 + 2 * gc] =
                make_float2(o[mt][nt][2] * inv1, o[mt][nt][3] * inv1);
        }
    }
}

extern "C" void kernel_launch(void* const* d_in, const int* in_sizes, int n_in,
                              void* d_out, int out_size) {
    (void)in_sizes; (void)n_in; (void)out_size;
    const float4* Q = (const float4*)d_in[0];
    const float4* K = (const float4*)d_in[1];
    const float4* V = (const float4*)d_in[2];
    float* O = (float*)d_out;

    prepass_qkv<<<2048, 256>>>(Q, K, V);

    static int attr_set = 0;
    if (!attr_set) {
        cudaFuncSetAttribute(flash_sdpa_f16,
                             cudaFuncAttributeMaxDynamicSharedMemorySize, SMEM_BYTES);
        attr_set = 1;
    }
    dim3 grid(SEQ / BM, NBH);   // 16 x 64 = 1024 CTAs
    flash_sdpa_f16<<<grid, 128, SMEM_BYTES>>>(O);
}